// round 13
// baseline (speedup 1.0000x reference)
#include <cuda_runtime.h>
#include <cuda_bf16.h>

typedef unsigned int u32;

#define Tq 28
#define Iq 28
#define Hq 128
#define Cq 10

#define OFF_X0H 196608
#define OFF_X0L 204800
#define OFF_EX  212992
#define OFF_PART 218112
#define OFF_B0 229376
#define OFF_B1 229888
#define SMEM_DYN 230400

static __device__ __forceinline__ u32 smem_u32(const void* p) {
    u32 a; asm("{ .reg .u64 t; cvta.to.shared.u64 t, %1; cvt.u32.u64 %0, t; }" : "=r"(a) : "l"(p));
    return a;
}
static __device__ __forceinline__ float tanh_fast(float x) {
    float ax = fabsf(x), e = __expf(-2.f * ax);
    return copysignf(__fdividef(1.f - e, 1.f + e), x);
}
static __device__ __forceinline__ u32 pack_bf16x2(float lo, float hi) {
    u32 r; asm("cvt.rn.bf16x2.f32 %0, %1, %2;" : "=r"(r) : "f"(hi), "f"(lo)); return r;
}
static __device__ __forceinline__ float lo16f(u32 p) { return __uint_as_float(p << 16); }
static __device__ __forceinline__ float hi16f(u32 p) { return __uint_as_float(p & 0xFFFF0000u); }

static __device__ __forceinline__ void mma_bf16(float (&d)[4], const u32 (&a)[4], u32 b0, u32 b1) {
    asm volatile(
        "mma.sync.aligned.m16n8k16.row.col.f32.bf16.bf16.f32 "
        "{%0,%1,%2,%3}, {%4,%5,%6,%7}, {%8,%9}, {%0,%1,%2,%3};"
        : "+f"(d[0]), "+f"(d[1]), "+f"(d[2]), "+f"(d[3])
        : "r"(a[0]), "r"(a[1]), "r"(a[2]), "r"(a[3]), "r"(b0), "r"(b1));
}
#define LDMX4(r0, r1, r2, r3, addr) \
    asm volatile("ldmatrix.sync.aligned.m8n8.x4.shared.b16 {%0,%1,%2,%3}, [%4];" \
        : "=r"(r0), "=r"(r1), "=r"(r2), "=r"(r3) : "r"(addr))
#define STS128(addr, r) \
    asm volatile("st.shared.v4.b32 [%0], {%1,%2,%3,%4};" \
        :: "r"(addr), "r"((r)[0]), "r"((r)[1]), "r"((r)[2]), "r"((r)[3]) : "memory")
#define LDS128(r, addr) \
    asm volatile("ld.shared.v4.b32 {%0,%1,%2,%3}, [%4];" \
        : "=r"((r)[0]), "=r"((r)[1]), "=r"((r)[2]), "=r"((r)[3]) : "r"(addr) : "memory")
#define BARS(id) asm volatile("bar.sync %0, 64;" :: "r"(id) : "memory")

// k-half of the 3-term GEMM: kt in [ktb, ktb+4)
static __device__ __forceinline__ void gemm3_half(float (&D)[8][4],
                                                  const u32 (&Ah)[8][4], const u32 (&Al)[8][4],
                                                  u32 whb, u32 wlb, u32 hsR, u32 sw56, int ktb)
{
    #pragma unroll
    for (int k2 = 0; k2 < 4; k2++) {
        const int kt = ktb + k2;
        u32 cx = ((u32)(kt * 32) ^ sw56) + hsR;
        #pragma unroll
        for (int np = 0; np < 4; np++) {
            u32 off = (u32)(np * 4096) + cx;
            u32 bh0, bh1, bh2, bh3, bl0, bl1, bl2, bl3;
            LDMX4(bh0, bh1, bh2, bh3, whb + off);
            LDMX4(bl0, bl1, bl2, bl3, wlb + off);
            mma_bf16(D[2 * np],     Ah[kt], bh0, bh1);
            mma_bf16(D[2 * np],     Al[kt], bh0, bh1);
            mma_bf16(D[2 * np],     Ah[kt], bl0, bl1);
            mma_bf16(D[2 * np + 1], Ah[kt], bh2, bh3);
            mma_bf16(D[2 * np + 1], Al[kt], bh2, bh3);
            mma_bf16(D[2 * np + 1], Ah[kt], bl2, bl3);
        }
    }
}
// x GEMM: K=32 (2 k-chunks), 64B-row swizzled X tile.
static __device__ __forceinline__ void gemm_x(float (&D)[8][4],
                                              const u32 (&Ah)[2][4], const u32 (&Al)[2][4],
                                              u32 xhb, u32 xlb, u32 hsX, u32 sw5x)
{
    #pragma unroll
    for (int kt = 0; kt < 2; kt++) {
        u32 cx = ((u32)(kt * 32) ^ sw5x) + hsX;
        #pragma unroll
        for (int np = 0; np < 4; np++) {
            u32 off = (u32)(np * 1024) + cx;
            u32 bh0, bh1, bh2, bh3, bl0, bl1, bl2, bl3;
            LDMX4(bh0, bh1, bh2, bh3, xhb + off);
            LDMX4(bl0, bl1, bl2, bl3, xlb + off);
            mma_bf16(D[2 * np],     Ah[kt], bh0, bh1);
            mma_bf16(D[2 * np],     Al[kt], bh0, bh1);
            mma_bf16(D[2 * np],     Ah[kt], bl0, bl1);
            mma_bf16(D[2 * np + 1], Ah[kt], bh2, bh3);
            mma_bf16(D[2 * np + 1], Al[kt], bh2, bh3);
            mma_bf16(D[2 * np + 1], Ah[kt], bl2, bl3);
        }
    }
}
static __device__ __forceinline__ void tanh_pack(const float (&D)[8][4],
                                                 u32 (&hh)[8][4], u32 (&hl)[8][4], int base)
{
    #pragma unroll
    for (int ktl = 0; ktl < 4; ktl++) {
        #pragma unroll
        for (int o = 0; o < 2; o++) {
            int nt = 2 * ktl + o;
            float v0 = tanh_fast(D[nt][0]), v1 = tanh_fast(D[nt][1]);
            float v2 = tanh_fast(D[nt][2]), v3 = tanh_fast(D[nt][3]);
            u32 p01 = pack_bf16x2(v0, v1), p23 = pack_bf16x2(v2, v3);
            hh[base + ktl][2 * o] = p01;  hh[base + ktl][2 * o + 1] = p23;
            hl[base + ktl][2 * o]     = pack_bf16x2(v0 - lo16f(p01), v1 - hi16f(p01));
            hl[base + ktl][2 * o + 1] = pack_bf16x2(v2 - lo16f(p23), v3 - hi16f(p23));
        }
    }
}
// one-sided exchange halves
static __device__ __forceinline__ void stsx(u32 exOwn, const u32 (&h)[8][4], int own) {
    #pragma unroll
    for (int k = 0; k < 4; k++) STS128(exOwn + k * 512, h[own + k]);
}
static __device__ __forceinline__ void ldsx(u32 exOth, u32 (&h)[8][4], int oth) {
    #pragma unroll
    for (int k = 0; k < 4; k++) LDS128(h[oth + k], exOth + k * 512);
}

__global__ void __launch_bounds__(256, 1) rnn_fused(
    const float* __restrict__ x,
    const float* __restrict__ W_ih0, const float* __restrict__ W_hh0,
    const float* __restrict__ b_ih0, const float* __restrict__ b_hh0,
    const float* __restrict__ W_ih1, const float* __restrict__ W_hh1,
    const float* __restrict__ b_ih1, const float* __restrict__ b_hh1,
    const float* __restrict__ fc_w,  const float* __restrict__ fc_b,
    float* __restrict__ out)
{
    extern __shared__ char dyn[];
    const int tid = threadIdx.x;
    const int wid = tid >> 5, lane = tid & 31;
    const int rg = wid & 3, jh = wid >> 2;   // measured-best pairing
    const int g = lane >> 2, p = lane & 3;

    // ---- init: W tiles bf16 hi/lo, swizzled ----
    {
        const float* Ws[3] = { W_hh0, W_ih1, W_hh1 };
        #pragma unroll
        for (int m = 0; m < 3; m++) {
            char* dh = dyn + (2 * m) * 32768;
            char* dl = dyn + (2 * m + 1) * 32768;
            const float* W = Ws[m];
            for (int i = tid; i < Hq * Hq; i += 256) {
                int j = i >> 7, k = i & 127;
                float v = W[i];
                __nv_bfloat16 hb = __float2bfloat16(v);
                u32 a = (u32)(j * 256) + (u32)((2 * k) ^ ((j & 7) << 4));
                *(__nv_bfloat16*)(dh + a) = hb;
                *(__nv_bfloat16*)(dl + a) = __float2bfloat16(v - __bfloat162float(hb));
            }
        }
        for (int i = tid; i < Hq * 32; i += 256) {
            int j = i >> 5, k = i & 31;
            float v = (k < Iq) ? W_ih0[j * Iq + k] : 0.0f;
            __nv_bfloat16 hb = __float2bfloat16(v);
            u32 a = (u32)(j * 64) + (u32)((2 * k) ^ ((j & 3) << 4));
            *(__nv_bfloat16*)(dyn + OFF_X0H + a) = hb;
            *(__nv_bfloat16*)(dyn + OFF_X0L + a) = __float2bfloat16(v - __bfloat162float(hb));
        }
        float* b0s = (float*)(dyn + OFF_B0);
        float* b1s = (float*)(dyn + OFF_B1);
        for (int i = tid; i < Hq; i += 256) {
            b0s[i] = b_ih0[i] + b_hh0[i];
            b1s[i] = b_ih1[i] + b_hh1[i];
        }
    }
    __syncthreads();

    const u32 smb = smem_u32(dyn);
    const u32 r    = (u32)((((lane >> 4) & 1) * 8) + (lane & 7));
    const u32 h16  = (u32)(((lane >> 3) & 1) * 16);
    const u32 swzR = (u32)((lane & 7) << 4);
    const u32 hsR  = r * 256 + (h16 ^ (swzR & 16));
    const u32 sw56 = swzR & 96;
    const u32 swzX = (u32)((lane & 3) << 4);
    const u32 hsX  = r * 64 + (h16 ^ (swzX & 16));
    const u32 sw5x = swzX & 32;

    const u32 W0H = smb + (u32)(jh * 16384),           W0L = smb + 32768  + (u32)(jh * 16384);
    const u32 WIH = smb + 65536 + (u32)(jh * 16384),   WIL = smb + 98304  + (u32)(jh * 16384);
    const u32 WHH = smb + 131072 + (u32)(jh * 16384),  WHL = smb + 163840 + (u32)(jh * 16384);
    const u32 X0H = smb + OFF_X0H + (u32)(jh * 4096),  X0L = smb + OFF_X0L + (u32)(jh * 4096);
    const u32 exOwn = smb + OFF_EX + (u32)((((rg * 2 + jh) * 4) * 32 + lane) * 16);
    const u32 exOth = smb + OFF_EX + (u32)((((rg * 2 + 1 - jh) * 4) * 32 + lane) * 16);
    const int own = jh * 4, oth = (1 - jh) * 4, barid = rg + 1;

    const float* b0s = (float*)(dyn + OFF_B0);
    const float* b1s = (float*)(dyn + OFF_B1);
    const size_t rowA = ((size_t)blockIdx.x * 4 + rg) * 16 + g;
    const float* xA = x + rowA * Tq * Iq;
    const float* xB = x + (rowA + 8) * Tq * Iq;

    u32 h0h[8][4], h0l[8][4], h1h[8][4], h1l[8][4];
    float D[8][4];

    for (int t = 0; t < Tq; t++) {
        // ---- x A-frags (K=32) ----
        u32 xh[2][4], xl[2][4];
        {
            const float* at = xA + t * Iq;
            const float* bt = xB + t * Iq;
            float2 xv[8];
            xv[0] = *(const float2*)(at + 2 * p);       xv[1] = *(const float2*)(bt + 2 * p);
            xv[2] = *(const float2*)(at + 8 + 2 * p);   xv[3] = *(const float2*)(bt + 8 + 2 * p);
            xv[4] = *(const float2*)(at + 16 + 2 * p);  xv[5] = *(const float2*)(bt + 16 + 2 * p);
            xv[6] = (p < 2) ? *(const float2*)(at + 24 + 2 * p) : make_float2(0.f, 0.f);
            xv[7] = (p < 2) ? *(const float2*)(bt + 24 + 2 * p) : make_float2(0.f, 0.f);
            #pragma unroll
            for (int q = 0; q < 8; q++) {
                u32 hu = pack_bf16x2(xv[q].x, xv[q].y);
                xh[q >> 2][q & 3] = hu;
                xl[q >> 2][q & 3] = pack_bf16x2(xv[q].x - lo16f(hu), xv[q].y - hi16f(hu));
            }
        }

        // ---- layer 0: D = b0 + h0@W0^T + x@Wih0^T, h1-exchange of step t-1 hidden inside ----
        #pragma unroll
        for (int nt = 0; nt < 8; nt++) {
            float2 bv = *(const float2*)&b0s[jh * 64 + nt * 8 + p * 2];
            D[nt][0] = bv.x; D[nt][1] = bv.y; D[nt][2] = bv.x; D[nt][3] = bv.y;
        }
        if (t > 0) {
            gemm3_half(D, h0h, h0l, W0H, W0L, hsR, sw56, 0);
            BARS(barid);                 // partner's h1h STS (end of t-1) is visible
            ldsx(exOth, h1h, oth);
            BARS(barid);
            stsx(exOwn, h1l, own);       // begin h1-lo exchange
            gemm3_half(D, h0h, h0l, W0H, W0L, hsR, sw56, 4);
            BARS(barid);
            ldsx(exOth, h1l, oth);
            BARS(barid);
        }
        gemm_x(D, xh, xl, X0H, X0L, hsX, sw5x);

        // ---- h0_new: tanh+pack, then exchange hidden under the Whh1 gemm ----
        tanh_pack(D, h0h, h0l, own);
        stsx(exOwn, h0h, own);

        #pragma unroll
        for (int nt = 0; nt < 8; nt++) {
            float2 bv = *(const float2*)&b1s[jh * 64 + nt * 8 + p * 2];
            D[nt][0] = bv.x; D[nt][1] = bv.y; D[nt][2] = bv.x; D[nt][3] = bv.y;
        }
        if (t > 0) gemm3_half(D, h1h, h1l, WHH, WHL, hsR, sw56, 0);
        BARS(barid);
        ldsx(exOth, h0h, oth);
        BARS(barid);
        stsx(exOwn, h0l, own);
        if (t > 0) gemm3_half(D, h1h, h1l, WHH, WHL, hsR, sw56, 4);
        BARS(barid);
        ldsx(exOth, h0l, oth);
        BARS(barid);

        // ---- layer 1 input term (needs complete h0) ----
        gemm3_half(D, h0h, h0l, WIH, WIL, hsR, sw56, 0);
        gemm3_half(D, h0h, h0l, WIH, WIL, hsR, sw56, 4);

        if (t < Tq - 1) {
            tanh_pack(D, h1h, h1l, own);
            stsx(exOwn, h1h, own);       // h1-hi exchange completes early next step
        } else {
            #pragma unroll
            for (int nt = 0; nt < 8; nt++)
                #pragma unroll
                for (int q = 0; q < 4; q++) D[nt][q] = tanh_fast(D[nt][q]);
        }
    }

    // ---- FC: out = h1 @ fc_w^T + fc_b ----
    __syncthreads();
    float* fcs  = (float*)(dyn + OFF_EX);
    float* part = (float*)(dyn + OFF_PART);
    for (int i = tid; i < Cq * Hq; i += 256) fcs[i] = fc_w[i];
    __syncthreads();

    float accA[Cq], accB[Cq];
    #pragma unroll
    for (int c = 0; c < Cq; c++) { accA[c] = 0.f; accB[c] = 0.f; }
    #pragma unroll
    for (int nt = 0; nt < 8; nt++) {
        int j = jh * 64 + nt * 8 + p * 2;
        #pragma unroll
        for (int c = 0; c < Cq; c++) {
            float2 fw = *(const float2*)&fcs[c * Hq + j];
            accA[c] = fmaf(D[nt][0], fw.x, fmaf(D[nt][1], fw.y, accA[c]));
            accB[c] = fmaf(D[nt][2], fw.x, fmaf(D[nt][3], fw.y, accB[c]));
        }
    }
    #pragma unroll
    for (int c = 0; c < Cq; c++) {
        accA[c] += __shfl_xor_sync(0xFFFFFFFFu, accA[c], 1);
        accA[c] += __shfl_xor_sync(0xFFFFFFFFu, accA[c], 2);
        accB[c] += __shfl_xor_sync(0xFFFFFFFFu, accB[c], 1);
        accB[c] += __shfl_xor_sync(0xFFFFFFFFu, accB[c], 2);
    }
    if (p == 0) {
        int base = (rg * 2 + jh) * 16;
        #pragma unroll
        for (int c = 0; c < Cq; c++) {
            part[(base + g) * Cq + c]     = accA[c];
            part[(base + g + 8) * Cq + c] = accB[c];
        }
    }
    __syncthreads();
    for (int i = tid; i < 64 * Cq; i += 256) {
        int row = i / Cq, c = i - row * Cq;
        int rg2 = row >> 4, rr = row & 15;
        float v = fc_b[c] + part[((rg2 * 2) * 16 + rr) * Cq + c]
                          + part[((rg2 * 2 + 1) * 16 + rr) * Cq + c];
        out[((size_t)blockIdx.x * 64 + row) * Cq + c] = v;
    }
}

extern "C" void kernel_launch(void* const* d_in, const int* in_sizes, int n_in,
                              void* d_out, int out_size) {
    const float* x     = (const float*)d_in[0];
    const float* W_ih0 = (const float*)d_in[1];
    const float* W_hh0 = (const float*)d_in[2];
    const float* b_ih0 = (const float*)d_in[3];
    const float* b_hh0 = (const float*)d_in[4];
    const float* W_ih1 = (const float*)d_in[5];
    const float* W_hh1 = (const float*)d_in[6];
    const float* b_ih1 = (const float*)d_in[7];
    const float* b_hh1 = (const float*)d_in[8];
    const float* fc_w  = (const float*)d_in[9];
    const float* fc_b  = (const float*)d_in[10];
    float* out = (float*)d_out;

    cudaFuncSetAttribute(rnn_fused, cudaFuncAttributeMaxDynamicSharedMemorySize, SMEM_DYN);
    rnn_fused<<<128, 256, SMEM_DYN>>>(x, W_ih0, W_hh0, b_ih0, b_hh0,
                                      W_ih1, W_hh1, b_ih1, b_hh1, fc_w, fc_b, out);
}

// round 14
// speedup vs baseline: 1.3240x; 1.3240x over previous
#include <cuda_runtime.h>
#include <cuda_bf16.h>
#include <cuda_fp16.h>

typedef unsigned int u32;

#define Tq 28
#define Iq 28
#define Hq 128
#define Cq 10

// SMEM map (bytes): W0@0 WI@32768 WH@65536 (fp16, 256B-row swizzle)
// X0@98304 (fp16, 64B-row swizzle) | exch@106496 (16K; FC reuse: fcw@106496, part@111616)
// b0@122880 b1@123392
#define OFF_X0  98304
#define OFF_EX  106496
#define OFF_PART 111616
#define OFF_B0  122880
#define OFF_B1  123392
#define SMEM_DYN 123904

static __device__ __forceinline__ u32 smem_u32(const void* p) {
    u32 a; asm("{ .reg .u64 t; cvta.to.shared.u64 t, %1; cvt.u32.u64 %0, t; }" : "=r"(a) : "l"(p));
    return a;
}
static __device__ __forceinline__ float tanh_fast(float x) {
    float ax = fabsf(x), e = __expf(-2.f * ax);
    return copysignf(__fdividef(1.f - e, 1.f + e), x);
}
// pack {lo_elem, hi_elem} -> f16x2 (lo_elem in low 16 bits)
static __device__ __forceinline__ u32 pack_f16x2(float lo, float hi) {
    u32 r; asm("cvt.rn.f16x2.f32 %0, %1, %2;" : "=r"(r) : "f"(hi), "f"(lo)); return r;
}
static __device__ __forceinline__ float2 f16x2_to_f2(u32 p) {
    __half2 h = *reinterpret_cast<__half2*>(&p);
    return __half22float2(h);
}

static __device__ __forceinline__ void mma_f16(float (&d)[4], const u32 (&a)[4], u32 b0, u32 b1) {
    asm volatile(
        "mma.sync.aligned.m16n8k16.row.col.f32.f16.f16.f32 "
        "{%0,%1,%2,%3}, {%4,%5,%6,%7}, {%8,%9}, {%0,%1,%2,%3};"
        : "+f"(d[0]), "+f"(d[1]), "+f"(d[2]), "+f"(d[3])
        : "r"(a[0]), "r"(a[1]), "r"(a[2]), "r"(a[3]), "r"(b0), "r"(b1));
}
#define LDMX4(r0, r1, r2, r3, addr) \
    asm volatile("ldmatrix.sync.aligned.m8n8.x4.shared.b16 {%0,%1,%2,%3}, [%4];" \
        : "=r"(r0), "=r"(r1), "=r"(r2), "=r"(r3) : "r"(addr))
#define STS128(addr, r) \
    asm volatile("st.shared.v4.b32 [%0], {%1,%2,%3,%4};" \
        :: "r"(addr), "r"((r)[0]), "r"((r)[1]), "r"((r)[2]), "r"((r)[3]) : "memory")
#define LDS128(r, addr) \
    asm volatile("ld.shared.v4.b32 {%0,%1,%2,%3}, [%4];" \
        : "=r"((r)[0]), "=r"((r)[1]), "=r"((r)[2]), "=r"((r)[3]) : "r"(addr) : "memory")
#define BARS(id) asm volatile("bar.sync %0, 64;" :: "r"(id) : "memory")

// 2-term GEMM: D[8][4] += (Ah + Al) @ W^T, W fp16 single, over this warp's 64 j-cols.
static __device__ __forceinline__ void gemm2h(float (&D)[8][4],
                                              const u32 (&Ah)[8][4], const u32 (&Al)[8][4],
                                              u32 wb, u32 hsR, u32 sw56)
{
    #pragma unroll
    for (int kt = 0; kt < 8; kt++) {
        u32 cx = ((u32)(kt * 32) ^ sw56) + hsR;
        #pragma unroll
        for (int np = 0; np < 4; np++) {
            u32 off = (u32)(np * 4096) + cx;
            u32 b0, b1, b2, b3;
            LDMX4(b0, b1, b2, b3, wb + off);
            mma_f16(D[2 * np],     Ah[kt], b0, b1);
            mma_f16(D[2 * np],     Al[kt], b0, b1);
            mma_f16(D[2 * np + 1], Ah[kt], b2, b3);
            mma_f16(D[2 * np + 1], Al[kt], b2, b3);
        }
    }
}
// x GEMM: K=32 (2 k-chunks), 64B-row swizzled X tile, W fp16 single.
static __device__ __forceinline__ void gemm_x2(float (&D)[8][4],
                                               const u32 (&Ah)[2][4], const u32 (&Al)[2][4],
                                               u32 xb, u32 hsX, u32 sw5x)
{
    #pragma unroll
    for (int kt = 0; kt < 2; kt++) {
        u32 cx = ((u32)(kt * 32) ^ sw5x) + hsX;
        #pragma unroll
        for (int np = 0; np < 4; np++) {
            u32 off = (u32)(np * 1024) + cx;
            u32 b0, b1, b2, b3;
            LDMX4(b0, b1, b2, b3, xb + off);
            mma_f16(D[2 * np],     Ah[kt], b0, b1);
            mma_f16(D[2 * np],     Al[kt], b0, b1);
            mma_f16(D[2 * np + 1], Ah[kt], b2, b3);
            mma_f16(D[2 * np + 1], Al[kt], b2, b3);
        }
    }
}
// tanh epilogue: D (own 64 cols) -> fp16 hi/lo A-frag chunks [base..base+3]
static __device__ __forceinline__ void tanh_pack(const float (&D)[8][4],
                                                 u32 (&hh)[8][4], u32 (&hl)[8][4], int base)
{
    #pragma unroll
    for (int ktl = 0; ktl < 4; ktl++) {
        #pragma unroll
        for (int o = 0; o < 2; o++) {
            int nt = 2 * ktl + o;
            float v0 = tanh_fast(D[nt][0]), v1 = tanh_fast(D[nt][1]);
            float v2 = tanh_fast(D[nt][2]), v3 = tanh_fast(D[nt][3]);
            u32 p01 = pack_f16x2(v0, v1), p23 = pack_f16x2(v2, v3);
            hh[base + ktl][2 * o] = p01;  hh[base + ktl][2 * o + 1] = p23;
            float2 a01 = f16x2_to_f2(p01), a23 = f16x2_to_f2(p23);
            hl[base + ktl][2 * o]     = pack_f16x2(v0 - a01.x, v1 - a01.y);
            hl[base + ktl][2 * o + 1] = pack_f16x2(v2 - a23.x, v3 - a23.y);
        }
    }
}
// pairwise hi/lo fragment exchange through SMEM
static __device__ __forceinline__ void xchg(u32 (&hh)[8][4], u32 (&hl)[8][4],
                                            u32 exOwn, u32 exOth, int own, int oth, int barid)
{
    #pragma unroll
    for (int k = 0; k < 4; k++) STS128(exOwn + k * 512, hh[own + k]);
    BARS(barid);
    #pragma unroll
    for (int k = 0; k < 4; k++) LDS128(hh[oth + k], exOth + k * 512);
    BARS(barid);
    #pragma unroll
    for (int k = 0; k < 4; k++) STS128(exOwn + k * 512, hl[own + k]);
    BARS(barid);
    #pragma unroll
    for (int k = 0; k < 4; k++) LDS128(hl[oth + k], exOth + k * 512);
    BARS(barid);
}

__global__ void __launch_bounds__(256, 1) rnn_fused(
    const float* __restrict__ x,
    const float* __restrict__ W_ih0, const float* __restrict__ W_hh0,
    const float* __restrict__ b_ih0, const float* __restrict__ b_hh0,
    const float* __restrict__ W_ih1, const float* __restrict__ W_hh1,
    const float* __restrict__ b_ih1, const float* __restrict__ b_hh1,
    const float* __restrict__ fc_w,  const float* __restrict__ fc_b,
    float* __restrict__ out)
{
    extern __shared__ char dyn[];
    const int tid = threadIdx.x;
    const int wid = tid >> 5, lane = tid & 31;
    const int rg = wid & 3, jh = wid >> 2;   // measured-best pairing
    const int g = lane >> 2, p = lane & 3;

    // ---- init: W tiles fp16, swizzled 256B rows ----
    {
        const float* Ws[3] = { W_hh0, W_ih1, W_hh1 };
        #pragma unroll
        for (int m = 0; m < 3; m++) {
            char* dw = dyn + m * 32768;
            const float* W = Ws[m];
            for (int i = tid; i < Hq * Hq; i += 256) {
                int j = i >> 7, k = i & 127;
                u32 a = (u32)(j * 256) + (u32)((2 * k) ^ ((j & 7) << 4));
                *(__half*)(dw + a) = __float2half(W[i]);
            }
        }
        for (int i = tid; i < Hq * 32; i += 256) {   // X tile [j][k pad32], 64B rows
            int j = i >> 5, k = i & 31;
            float v = (k < Iq) ? W_ih0[j * Iq + k] : 0.0f;
            u32 a = (u32)(j * 64) + (u32)((2 * k) ^ ((j & 3) << 4));
            *(__half*)(dyn + OFF_X0 + a) = __float2half(v);
        }
        float* b0s = (float*)(dyn + OFF_B0);
        float* b1s = (float*)(dyn + OFF_B1);
        for (int i = tid; i < Hq; i += 256) {
            b0s[i] = b_ih0[i] + b_hh0[i];
            b1s[i] = b_ih1[i] + b_hh1[i];
        }
    }
    __syncthreads();

    const u32 smb = smem_u32(dyn);
    const u32 r    = (u32)((((lane >> 4) & 1) * 8) + (lane & 7));
    const u32 h16  = (u32)(((lane >> 3) & 1) * 16);
    const u32 swzR = (u32)((lane & 7) << 4);
    const u32 hsR  = r * 256 + (h16 ^ (swzR & 16));
    const u32 sw56 = swzR & 96;
    const u32 swzX = (u32)((lane & 3) << 4);
    const u32 hsX  = r * 64 + (h16 ^ (swzX & 16));
    const u32 sw5x = swzX & 32;

    const u32 W0B = smb + (u32)(jh * 16384);
    const u32 WIB = smb + 32768 + (u32)(jh * 16384);
    const u32 WHB = smb + 65536 + (u32)(jh * 16384);
    const u32 X0B = smb + OFF_X0 + (u32)(jh * 4096);
    const u32 exOwn = smb + OFF_EX + (u32)((((rg * 2 + jh) * 4) * 32 + lane) * 16);
    const u32 exOth = smb + OFF_EX + (u32)((((rg * 2 + 1 - jh) * 4) * 32 + lane) * 16);
    const int own = jh * 4, oth = (1 - jh) * 4, barid = rg + 1;

    const float* b0s = (float*)(dyn + OFF_B0);
    const float* b1s = (float*)(dyn + OFF_B1);
    const size_t rowA = ((size_t)blockIdx.x * 4 + rg) * 16 + g;
    const float* xA = x + rowA * Tq * Iq;
    const float* xB = x + (rowA + 8) * Tq * Iq;

    u32 h0h[8][4], h0l[8][4], h1h[8][4], h1l[8][4];
    float D[8][4];

    for (int t = 0; t < Tq; t++) {
        // ---- x A-frags (K=32, fp16 hi/lo) ----
        u32 xh[2][4], xl[2][4];
        {
            const float* at = xA + t * Iq;
            const float* bt = xB + t * Iq;
            float2 xv[8];
            xv[0] = *(const float2*)(at + 2 * p);       xv[1] = *(const float2*)(bt + 2 * p);
            xv[2] = *(const float2*)(at + 8 + 2 * p);   xv[3] = *(const float2*)(bt + 8 + 2 * p);
            xv[4] = *(const float2*)(at + 16 + 2 * p);  xv[5] = *(const float2*)(bt + 16 + 2 * p);
            xv[6] = (p < 2) ? *(const float2*)(at + 24 + 2 * p) : make_float2(0.f, 0.f);
            xv[7] = (p < 2) ? *(const float2*)(bt + 24 + 2 * p) : make_float2(0.f, 0.f);
            #pragma unroll
            for (int q = 0; q < 8; q++) {
                u32 hu = pack_f16x2(xv[q].x, xv[q].y);
                float2 av = f16x2_to_f2(hu);
                xh[q >> 2][q & 3] = hu;
                xl[q >> 2][q & 3] = pack_f16x2(xv[q].x - av.x, xv[q].y - av.y);
            }
        }

        // ---- layer 0: D = b0 + h0@W0^T + x@Wih0^T ----
        #pragma unroll
        for (int nt = 0; nt < 8; nt++) {
            float2 bv = *(const float2*)&b0s[jh * 64 + nt * 8 + p * 2];
            D[nt][0] = bv.x; D[nt][1] = bv.y; D[nt][2] = bv.x; D[nt][3] = bv.y;
        }
        if (t > 0) gemm2h(D, h0h, h0l, W0B, hsR, sw56);
        gemm_x2(D, xh, xl, X0B, hsX, sw5x);
        tanh_pack(D, h0h, h0l, own);
        xchg(h0h, h0l, exOwn, exOth, own, oth, barid);

        // ---- layer 1: D = b1 + h1@Whh1^T + h0@Wih1^T ----
        #pragma unroll
        for (int nt = 0; nt < 8; nt++) {
            float2 bv = *(const float2*)&b1s[jh * 64 + nt * 8 + p * 2];
            D[nt][0] = bv.x; D[nt][1] = bv.y; D[nt][2] = bv.x; D[nt][3] = bv.y;
        }
        if (t > 0) gemm2h(D, h1h, h1l, WHB, hsR, sw56);
        gemm2h(D, h0h, h0l, WIB, hsR, sw56);
        if (t < Tq - 1) {
            tanh_pack(D, h1h, h1l, own);
            xchg(h1h, h1l, exOwn, exOth, own, oth, barid);
        } else {
            #pragma unroll
            for (int nt = 0; nt < 8; nt++)
                #pragma unroll
                for (int q = 0; q < 4; q++) D[nt][q] = tanh_fast(D[nt][q]);
        }
    }

    // ---- FC: out = h1 @ fc_w^T + fc_b ----
    __syncthreads();
    float* fcs  = (float*)(dyn + OFF_EX);
    float* part = (float*)(dyn + OFF_PART);
    for (int i = tid; i < Cq * Hq; i += 256) fcs[i] = fc_w[i];
    __syncthreads();

    float accA[Cq], accB[Cq];
    #pragma unroll
    for (int c = 0; c < Cq; c++) { accA[c] = 0.f; accB[c] = 0.f; }
    #pragma unroll
    for (int nt = 0; nt < 8; nt++) {
        int j = jh * 64 + nt * 8 + p * 2;
        #pragma unroll
        for (int c = 0; c < Cq; c++) {
            float2 fw = *(const float2*)&fcs[c * Hq + j];
            accA[c] = fmaf(D[nt][0], fw.x, fmaf(D[nt][1], fw.y, accA[c]));
            accB[c] = fmaf(D[nt][2], fw.x, fmaf(D[nt][3], fw.y, accB[c]));
        }
    }
    #pragma unroll
    for (int c = 0; c < Cq; c++) {
        accA[c] += __shfl_xor_sync(0xFFFFFFFFu, accA[c], 1);
        accA[c] += __shfl_xor_sync(0xFFFFFFFFu, accA[c], 2);
        accB[c] += __shfl_xor_sync(0xFFFFFFFFu, accB[c], 1);
        accB[c] += __shfl_xor_sync(0xFFFFFFFFu, accB[c], 2);
    }
    if (p == 0) {
        int base = (rg * 2 + jh) * 16;
        #pragma unroll
        for (int c = 0; c < Cq; c++) {
            part[(base + g) * Cq + c]     = accA[c];
            part[(base + g + 8) * Cq + c] = accB[c];
        }
    }
    __syncthreads();
    for (int i = tid; i < 64 * Cq; i += 256) {
        int row = i / Cq, c = i - row * Cq;
        int rg2 = row >> 4, rr = row & 15;
        float v = fc_b[c] + part[((rg2 * 2) * 16 + rr) * Cq + c]
                          + part[((rg2 * 2 + 1) * 16 + rr) * Cq + c];
        out[((size_t)blockIdx.x * 64 + row) * Cq + c] = v;
    }
}

extern "C" void kernel_launch(void* const* d_in, const int* in_sizes, int n_in,
                              void* d_out, int out_size) {
    const float* x     = (const float*)d_in[0];
    const float* W_ih0 = (const float*)d_in[1];
    const float* W_hh0 = (const float*)d_in[2];
    const float* b_ih0 = (const float*)d_in[3];
    const float* b_hh0 = (const float*)d_in[4];
    const float* W_ih1 = (const float*)d_in[5];
    const float* W_hh1 = (const float*)d_in[6];
    const float* b_ih1 = (const float*)d_in[7];
    const float* b_hh1 = (const float*)d_in[8];
    const float* fc_w  = (const float*)d_in[9];
    const float* fc_b  = (const float*)d_in[10];
    float* out = (float*)d_out;

    cudaFuncSetAttribute(rnn_fused, cudaFuncAttributeMaxDynamicSharedMemorySize, SMEM_DYN);
    rnn_fused<<<128, 256, SMEM_DYN>>>(x, W_ih0, W_hh0, b_ih0, b_hh0,
                                      W_ih1, W_hh1, b_ih1, b_hh1, fc_w, fc_b, out);
}

// round 15
// speedup vs baseline: 1.4934x; 1.1279x over previous
#include <cuda_runtime.h>
#include <cuda_bf16.h>
#include <cuda_fp16.h>

typedef unsigned int u32;

#define Tq 28
#define Iq 28
#define Hq 128
#define Cq 10

// SMEM map (bytes): W0@0 WI@32768 WH@65536 (fp16, 256B-row swizzle)
// X0@98304 (fp16, 64B-row swizzle)
// EXA@106496 (32K, layer-0 exchange; FC reuse: fcw@EXA, part@EXA+5120)
// EXB@139264 (32K, layer-1 exchange)
// b0@172032 b1@172544
#define OFF_X0  98304
#define OFF_EXA 106496
#define OFF_EXB 139264
#define OFF_B0  172032
#define OFF_B1  172544
#define SMEM_DYN 173056

static __device__ __forceinline__ u32 smem_u32(const void* p) {
    u32 a; asm("{ .reg .u64 t; cvta.to.shared.u64 t, %1; cvt.u32.u64 %0, t; }" : "=r"(a) : "l"(p));
    return a;
}
static __device__ __forceinline__ float tanh_mufu(float x) {
    float y; asm("tanh.approx.f32 %0, %1;" : "=f"(y) : "f"(x)); return y;
}
// pack {lo_elem, hi_elem} -> f16x2 (lo_elem in low 16 bits)
static __device__ __forceinline__ u32 pack_f16x2(float lo, float hi) {
    u32 r; asm("cvt.rn.f16x2.f32 %0, %1, %2;" : "=r"(r) : "f"(hi), "f"(lo)); return r;
}
static __device__ __forceinline__ float2 f16x2_to_f2(u32 p) {
    __half2 h = *reinterpret_cast<__half2*>(&p);
    return __half22float2(h);
}

static __device__ __forceinline__ void mma_f16(float (&d)[4], const u32 (&a)[4], u32 b0, u32 b1) {
    asm volatile(
        "mma.sync.aligned.m16n8k16.row.col.f32.f16.f16.f32 "
        "{%0,%1,%2,%3}, {%4,%5,%6,%7}, {%8,%9}, {%0,%1,%2,%3};"
        : "+f"(d[0]), "+f"(d[1]), "+f"(d[2]), "+f"(d[3])
        : "r"(a[0]), "r"(a[1]), "r"(a[2]), "r"(a[3]), "r"(b0), "r"(b1));
}
#define LDMX4(r0, r1, r2, r3, addr) \
    asm volatile("ldmatrix.sync.aligned.m8n8.x4.shared.b16 {%0,%1,%2,%3}, [%4];" \
        : "=r"(r0), "=r"(r1), "=r"(r2), "=r"(r3) : "r"(addr))
#define STS128(addr, r) \
    asm volatile("st.shared.v4.b32 [%0], {%1,%2,%3,%4};" \
        :: "r"(addr), "r"((r)[0]), "r"((r)[1]), "r"((r)[2]), "r"((r)[3]) : "memory")
#define LDS128(r, addr) \
    asm volatile("ld.shared.v4.b32 {%0,%1,%2,%3}, [%4];" \
        : "=r"((r)[0]), "=r"((r)[1]), "=r"((r)[2]), "=r"((r)[3]) : "r"(addr) : "memory")
#define BARS(id) asm volatile("bar.sync %0, 64;" :: "r"(id) : "memory")

// 2-term GEMM: D[8][4] += (Ah + Al) @ W^T, W fp16 single, over this warp's 64 j-cols.
static __device__ __forceinline__ void gemm2h(float (&D)[8][4],
                                              const u32 (&Ah)[8][4], const u32 (&Al)[8][4],
                                              u32 wb, u32 hsR, u32 sw56)
{
    #pragma unroll
    for (int kt = 0; kt < 8; kt++) {
        u32 cx = ((u32)(kt * 32) ^ sw56) + hsR;
        #pragma unroll
        for (int np = 0; np < 4; np++) {
            u32 off = (u32)(np * 4096) + cx;
            u32 b0, b1, b2, b3;
            LDMX4(b0, b1, b2, b3, wb + off);
            mma_f16(D[2 * np],     Ah[kt], b0, b1);
            mma_f16(D[2 * np],     Al[kt], b0, b1);
            mma_f16(D[2 * np + 1], Ah[kt], b2, b3);
            mma_f16(D[2 * np + 1], Al[kt], b2, b3);
        }
    }
}
// x GEMM: K=32 (2 k-chunks), 64B-row swizzled X tile, W fp16 single.
static __device__ __forceinline__ void gemm_x2(float (&D)[8][4],
                                               const u32 (&Ah)[2][4], const u32 (&Al)[2][4],
                                               u32 xb, u32 hsX, u32 sw5x)
{
    #pragma unroll
    for (int kt = 0; kt < 2; kt++) {
        u32 cx = ((u32)(kt * 32) ^ sw5x) + hsX;
        #pragma unroll
        for (int np = 0; np < 4; np++) {
            u32 off = (u32)(np * 1024) + cx;
            u32 b0, b1, b2, b3;
            LDMX4(b0, b1, b2, b3, xb + off);
            mma_f16(D[2 * np],     Ah[kt], b0, b1);
            mma_f16(D[2 * np],     Al[kt], b0, b1);
            mma_f16(D[2 * np + 1], Ah[kt], b2, b3);
            mma_f16(D[2 * np + 1], Al[kt], b2, b3);
        }
    }
}
// tanh epilogue: D (own 64 cols) -> fp16 hi/lo A-frag chunks [base..base+3]
static __device__ __forceinline__ void tanh_pack(const float (&D)[8][4],
                                                 u32 (&hh)[8][4], u32 (&hl)[8][4], int base)
{
    #pragma unroll
    for (int ktl = 0; ktl < 4; ktl++) {
        #pragma unroll
        for (int o = 0; o < 2; o++) {
            int nt = 2 * ktl + o;
            float v0 = tanh_mufu(D[nt][0]), v1 = tanh_mufu(D[nt][1]);
            float v2 = tanh_mufu(D[nt][2]), v3 = tanh_mufu(D[nt][3]);
            u32 p01 = pack_f16x2(v0, v1), p23 = pack_f16x2(v2, v3);
            hh[base + ktl][2 * o] = p01;  hh[base + ktl][2 * o + 1] = p23;
            float2 a01 = f16x2_to_f2(p01), a23 = f16x2_to_f2(p23);
            hl[base + ktl][2 * o]     = pack_f16x2(v0 - a01.x, v1 - a01.y);
            hl[base + ktl][2 * o + 1] = pack_f16x2(v2 - a23.x, v3 - a23.y);
        }
    }
}
// single-barrier combined hi/lo exchange (double-buffered across call sites):
// write own 8 chunks (4 hi + 4 lo), one barrier, read partner's 8 chunks. No trailing
// barrier: this buffer's next reuse is 2 exchanges away, and the partner's next
// barrier arrival (program-order after its LDS here) proves the read completed.
static __device__ __forceinline__ void xchg1(u32 (&hh)[8][4], u32 (&hl)[8][4],
                                             u32 exOwn, u32 exOth, int own, int oth, int barid)
{
    #pragma unroll
    for (int k = 0; k < 4; k++) {
        STS128(exOwn + k * 512, hh[own + k]);
        STS128(exOwn + (k + 4) * 512, hl[own + k]);
    }
    BARS(barid);
    #pragma unroll
    for (int k = 0; k < 4; k++) {
        LDS128(hh[oth + k], exOth + k * 512);
        LDS128(hl[oth + k], exOth + (k + 4) * 512);
    }
}

__global__ void __launch_bounds__(256, 1) rnn_fused(
    const float* __restrict__ x,
    const float* __restrict__ W_ih0, const float* __restrict__ W_hh0,
    const float* __restrict__ b_ih0, const float* __restrict__ b_hh0,
    const float* __restrict__ W_ih1, const float* __restrict__ W_hh1,
    const float* __restrict__ b_ih1, const float* __restrict__ b_hh1,
    const float* __restrict__ fc_w,  const float* __restrict__ fc_b,
    float* __restrict__ out)
{
    extern __shared__ char dyn[];
    const int tid = threadIdx.x;
    const int wid = tid >> 5, lane = tid & 31;
    const int rg = wid & 3, jh = wid >> 2;   // measured-best pairing
    const int g = lane >> 2, p = lane & 3;

    // ---- init: W tiles fp16, swizzled 256B rows ----
    {
        const float* Ws[3] = { W_hh0, W_ih1, W_hh1 };
        #pragma unroll
        for (int m = 0; m < 3; m++) {
            char* dw = dyn + m * 32768;
            const float* W = Ws[m];
            for (int i = tid; i < Hq * Hq; i += 256) {
                int j = i >> 7, k = i & 127;
                u32 a = (u32)(j * 256) + (u32)((2 * k) ^ ((j & 7) << 4));
                *(__half*)(dw + a) = __float2half(W[i]);
            }
        }
        for (int i = tid; i < Hq * 32; i += 256) {   // X tile [j][k pad32], 64B rows
            int j = i >> 5, k = i & 31;
            float v = (k < Iq) ? W_ih0[j * Iq + k] : 0.0f;
            u32 a = (u32)(j * 64) + (u32)((2 * k) ^ ((j & 3) << 4));
            *(__half*)(dyn + OFF_X0 + a) = __float2half(v);
        }
        float* b0s = (float*)(dyn + OFF_B0);
        float* b1s = (float*)(dyn + OFF_B1);
        for (int i = tid; i < Hq; i += 256) {
            b0s[i] = b_ih0[i] + b_hh0[i];
            b1s[i] = b_ih1[i] + b_hh1[i];
        }
    }
    __syncthreads();

    const u32 smb = smem_u32(dyn);
    const u32 r    = (u32)((((lane >> 4) & 1) * 8) + (lane & 7));
    const u32 h16  = (u32)(((lane >> 3) & 1) * 16);
    const u32 swzR = (u32)((lane & 7) << 4);
    const u32 hsR  = r * 256 + (h16 ^ (swzR & 16));
    const u32 sw56 = swzR & 96;
    const u32 swzX = (u32)((lane & 3) << 4);
    const u32 hsX  = r * 64 + (h16 ^ (swzX & 16));
    const u32 sw5x = swzX & 32;

    const u32 W0B = smb + (u32)(jh * 16384);
    const u32 WIB = smb + 32768 + (u32)(jh * 16384);
    const u32 WHB = smb + 65536 + (u32)(jh * 16384);
    const u32 X0B = smb + OFF_X0 + (u32)(jh * 4096);
    const u32 slotOwn = (u32)(((rg * 2 + jh) * 8) * 32 + lane) * 16;
    const u32 slotOth = (u32)(((rg * 2 + 1 - jh) * 8) * 32 + lane) * 16;
    const u32 exAOwn = smb + OFF_EXA + slotOwn, exAOth = smb + OFF_EXA + slotOth;
    const u32 exBOwn = smb + OFF_EXB + slotOwn, exBOth = smb + OFF_EXB + slotOth;
    const int own = jh * 4, oth = (1 - jh) * 4, barid = rg + 1;

    const float* b0s = (float*)(dyn + OFF_B0);
    const float* b1s = (float*)(dyn + OFF_B1);
    const size_t rowA = ((size_t)blockIdx.x * 4 + rg) * 16 + g;
    const float* xA = x + rowA * Tq * Iq;
    const float* xB = x + (rowA + 8) * Tq * Iq;

    u32 h0h[8][4], h0l[8][4], h1h[8][4], h1l[8][4];
    float D[8][4];

    for (int t = 0; t < Tq; t++) {
        // ---- x A-frags (K=32, fp16 hi/lo) ----
        u32 xh[2][4], xl[2][4];
        {
            const float* at = xA + t * Iq;
            const float* bt = xB + t * Iq;
            float2 xv[8];
            xv[0] = *(const float2*)(at + 2 * p);       xv[1] = *(const float2*)(bt + 2 * p);
            xv[2] = *(const float2*)(at + 8 + 2 * p);   xv[3] = *(const float2*)(bt + 8 + 2 * p);
            xv[4] = *(const float2*)(at + 16 + 2 * p);  xv[5] = *(const float2*)(bt + 16 + 2 * p);
            xv[6] = (p < 2) ? *(const float2*)(at + 24 + 2 * p) : make_float2(0.f, 0.f);
            xv[7] = (p < 2) ? *(const float2*)(bt + 24 + 2 * p) : make_float2(0.f, 0.f);
            #pragma unroll
            for (int q = 0; q < 8; q++) {
                u32 hu = pack_f16x2(xv[q].x, xv[q].y);
                float2 av = f16x2_to_f2(hu);
                xh[q >> 2][q & 3] = hu;
                xl[q >> 2][q & 3] = pack_f16x2(xv[q].x - av.x, xv[q].y - av.y);
            }
        }

        // ---- layer 0: D = b0 + h0@W0^T + x@Wih0^T ----
        #pragma unroll
        for (int nt = 0; nt < 8; nt++) {
            float2 bv = *(const float2*)&b0s[jh * 64 + nt * 8 + p * 2];
            D[nt][0] = bv.x; D[nt][1] = bv.y; D[nt][2] = bv.x; D[nt][3] = bv.y;
        }
        if (t > 0) gemm2h(D, h0h, h0l, W0B, hsR, sw56);
        gemm_x2(D, xh, xl, X0B, hsX, sw5x);
        tanh_pack(D, h0h, h0l, own);
        xchg1(h0h, h0l, exAOwn, exAOth, own, oth, barid);   // buffer A

        // ---- layer 1: D = b1 + h1@Whh1^T + h0@Wih1^T ----
        #pragma unroll
        for (int nt = 0; nt < 8; nt++) {
            float2 bv = *(const float2*)&b1s[jh * 64 + nt * 8 + p * 2];
            D[nt][0] = bv.x; D[nt][1] = bv.y; D[nt][2] = bv.x; D[nt][3] = bv.y;
        }
        if (t > 0) gemm2h(D, h1h, h1l, WHB, hsR, sw56);
        gemm2h(D, h0h, h0l, WIB, hsR, sw56);
        if (t < Tq - 1) {
            tanh_pack(D, h1h, h1l, own);
            xchg1(h1h, h1l, exBOwn, exBOth, own, oth, barid);  // buffer B
        } else {
            #pragma unroll
            for (int nt = 0; nt < 8; nt++)
                #pragma unroll
                for (int q = 0; q < 4; q++) D[nt][q] = tanh_mufu(D[nt][q]);
        }
    }

    // ---- FC: out = h1 @ fc_w^T + fc_b ----
    __syncthreads();
    float* fcs  = (float*)(dyn + OFF_EXA);
    float* part = (float*)(dyn + OFF_EXA + 5120);
    for (int i = tid; i < Cq * Hq; i += 256) fcs[i] = fc_w[i];
    __syncthreads();

    float accA[Cq], accB[Cq];
    #pragma unroll
    for (int c = 0; c < Cq; c++) { accA[c] = 0.f; accB[c] = 0.f; }
    #pragma unroll
    for (int nt = 0; nt < 8; nt++) {
        int j = jh * 64 + nt * 8 + p * 2;
        #pragma unroll
        for (int c = 0; c < Cq; c++) {
            float2 fw = *(const float2*)&fcs[c * Hq + j];
            accA[c] = fmaf(D[nt][0], fw.x, fmaf(D[nt][1], fw.y, accA[c]));
            accB[c] = fmaf(D[nt][2], fw.x, fmaf(D[nt][3], fw.y, accB[c]));
        }
    }
    #pragma unroll
    for (int c = 0; c < Cq; c++) {
        accA[c] += __shfl_xor_sync(0xFFFFFFFFu, accA[c], 1);
        accA[c] += __shfl_xor_sync(0xFFFFFFFFu, accA[c], 2);
        accB[c] += __shfl_xor_sync(0xFFFFFFFFu, accB[c], 1);
        accB[c] += __shfl_xor_sync(0xFFFFFFFFu, accB[c], 2);
    }
    if (p == 0) {
        int base = (rg * 2 + jh) * 16;
        #pragma unroll
        for (int c = 0; c < Cq; c++) {
            part[(base + g) * Cq + c]     = accA[c];
            part[(base + g + 8) * Cq + c] = accB[c];
        }
    }
    __syncthreads();
    for (int i = tid; i < 64 * Cq; i += 256) {
        int row = i / Cq, c = i - row * Cq;
        int rg2 = row >> 4, rr = row & 15;
        float v = fc_b[c] + part[((rg2 * 2) * 16 + rr) * Cq + c]
                          + part[((rg2 * 2 + 1) * 16 + rr) * Cq + c];
        out[((size_t)blockIdx.x * 64 + row) * Cq + c] = v;
    }
}

extern "C" void kernel_launch(void* const* d_in, const int* in_sizes, int n_in,
                              void* d_out, int out_size) {
    const float* x     = (const float*)d_in[0];
    const float* W_ih0 = (const float*)d_in[1];
    const float* W_hh0 = (const float*)d_in[2];
    const float* b_ih0 = (const float*)d_in[3];
    const float* b_hh0 = (const float*)d_in[4];
    const float* W_ih1 = (const float*)d_in[5];
    const float* W_hh1 = (const float*)d_in[6];
    const float* b_ih1 = (const float*)d_in[7];
    const float* b_hh1 = (const float*)d_in[8];
    const float* fc_w  = (const float*)d_in[9];
    const float* fc_b  = (const float*)d_in[10];
    float* out = (float*)d_out;

    cudaFuncSetAttribute(rnn_fused, cudaFuncAttributeMaxDynamicSharedMemorySize, SMEM_DYN);
    rnn_fused<<<128, 256, SMEM_DYN>>>(x, W_ih0, W_hh0, b_ih0, b_hh0,
                                      W_ih1, W_hh1, b_ih1, b_hh1, fc_w, fc_b, out);
}

// round 17
// speedup vs baseline: 1.4954x; 1.0014x over previous
#include <cuda_runtime.h>
#include <cuda_bf16.h>
#include <cuda_fp16.h>

typedef unsigned int u32;

#define Tq 28
#define Iq 28
#define Hq 128
#define Cq 10

// SMEM map (bytes): W0@0 WI@32768 WH@65536 (fp16, 256B-row swizzle)
// X0@98304 (fp16, 64B-row swizzle)
// EXA@106496 (32K, layer-0 exchange; FC reuse: fcw@EXA, part@EXA+5120)
// EXB@139264 (32K, layer-1 exchange)
// b0@172032 b1@172544
#define OFF_X0  98304
#define OFF_EXA 106496
#define OFF_EXB 139264
#define OFF_B0  172032
#define OFF_B1  172544
#define SMEM_DYN 173056

static __device__ __forceinline__ u32 smem_u32(const void* p) {
    u32 a; asm("{ .reg .u64 t; cvta.to.shared.u64 t, %1; cvt.u32.u64 %0, t; }" : "=r"(a) : "l"(p));
    return a;
}
static __device__ __forceinline__ float tanh_mufu(float x) {
    float y; asm("tanh.approx.f32 %0, %1;" : "=f"(y) : "f"(x)); return y;
}
// pack {lo_elem, hi_elem} -> f16x2 (lo_elem in low 16 bits)
static __device__ __forceinline__ u32 pack_f16x2(float lo, float hi) {
    u32 r; asm("cvt.rn.f16x2.f32 %0, %1, %2;" : "=r"(r) : "f"(hi), "f"(lo)); return r;
}
static __device__ __forceinline__ float2 f16x2_to_f2(u32 p) {
    __half2 h = *reinterpret_cast<__half2*>(&p);
    return __half22float2(h);
}

static __device__ __forceinline__ void mma_f16(float (&d)[4], const u32 (&a)[4], u32 b0, u32 b1) {
    asm volatile(
        "mma.sync.aligned.m16n8k16.row.col.f32.f16.f16.f32 "
        "{%0,%1,%2,%3}, {%4,%5,%6,%7}, {%8,%9}, {%0,%1,%2,%3};"
        : "+f"(d[0]), "+f"(d[1]), "+f"(d[2]), "+f"(d[3])
        : "r"(a[0]), "r"(a[1]), "r"(a[2]), "r"(a[3]), "r"(b0), "r"(b1));
}
#define LDMX4(r0, r1, r2, r3, addr) \
    asm volatile("ldmatrix.sync.aligned.m8n8.x4.shared.b16 {%0,%1,%2,%3}, [%4];" \
        : "=r"(r0), "=r"(r1), "=r"(r2), "=r"(r3) : "r"(addr))
#define STS128(addr, r) \
    asm volatile("st.shared.v4.b32 [%0], {%1,%2,%3,%4};" \
        :: "r"(addr), "r"((r)[0]), "r"((r)[1]), "r"((r)[2]), "r"((r)[3]) : "memory")
#define LDS128(r, addr) \
    asm volatile("ld.shared.v4.b32 {%0,%1,%2,%3}, [%4];" \
        : "=r"((r)[0]), "=r"((r)[1]), "=r"((r)[2]), "=r"((r)[3]) : "r"(addr) : "memory")
#define BARS(id) asm volatile("bar.sync %0, 64;" :: "r"(id) : "memory")

// 2-term GEMM, accumulator-interleaved: for each k-chunk load ALL 4 ldmatrix groups,
// then issue 8 mmas with Ah (D0..D7) then 8 with Al — same-accumulator RAW distance = 8
// mmas (~48cyc), hiding the HMMA accumulate latency that the naive order exposed.
static __device__ __forceinline__ void gemm2h(float (&D)[8][4],
                                              const u32 (&Ah)[8][4], const u32 (&Al)[8][4],
                                              u32 wb, u32 hsR, u32 sw56)
{
    #pragma unroll
    for (int kt = 0; kt < 8; kt++) {
        u32 cx = ((u32)(kt * 32) ^ sw56) + hsR;
        u32 b[4][4];
        #pragma unroll
        for (int np = 0; np < 4; np++)
            LDMX4(b[np][0], b[np][1], b[np][2], b[np][3], wb + (u32)(np * 4096) + cx);
        #pragma unroll
        for (int np = 0; np < 4; np++) {
            mma_f16(D[2 * np],     Ah[kt], b[np][0], b[np][1]);
            mma_f16(D[2 * np + 1], Ah[kt], b[np][2], b[np][3]);
        }
        #pragma unroll
        for (int np = 0; np < 4; np++) {
            mma_f16(D[2 * np],     Al[kt], b[np][0], b[np][1]);
            mma_f16(D[2 * np + 1], Al[kt], b[np][2], b[np][3]);
        }
    }
}
// x GEMM: K=32 (2 k-chunks), 64B-row swizzled X tile, same interleaving.
static __device__ __forceinline__ void gemm_x2(float (&D)[8][4],
                                               const u32 (&Ah)[2][4], const u32 (&Al)[2][4],
                                               u32 xb, u32 hsX, u32 sw5x)
{
    #pragma unroll
    for (int kt = 0; kt < 2; kt++) {
        u32 cx = ((u32)(kt * 32) ^ sw5x) + hsX;
        u32 b[4][4];
        #pragma unroll
        for (int np = 0; np < 4; np++)
            LDMX4(b[np][0], b[np][1], b[np][2], b[np][3], xb + (u32)(np * 1024) + cx);
        #pragma unroll
        for (int np = 0; np < 4; np++) {
            mma_f16(D[2 * np],     Ah[kt], b[np][0], b[np][1]);
            mma_f16(D[2 * np + 1], Ah[kt], b[np][2], b[np][3]);
        }
        #pragma unroll
        for (int np = 0; np < 4; np++) {
            mma_f16(D[2 * np],     Al[kt], b[np][0], b[np][1]);
            mma_f16(D[2 * np + 1], Al[kt], b[np][2], b[np][3]);
        }
    }
}
// tanh epilogue: D (own 64 cols) -> fp16 hi/lo A-frag chunks [base..base+3]
static __device__ __forceinline__ void tanh_pack(const float (&D)[8][4],
                                                 u32 (&hh)[8][4], u32 (&hl)[8][4], int base)
{
    #pragma unroll
    for (int ktl = 0; ktl < 4; ktl++) {
        #pragma unroll
        for (int o = 0; o < 2; o++) {
            int nt = 2 * ktl + o;
            float v0 = tanh_mufu(D[nt][0]), v1 = tanh_mufu(D[nt][1]);
            float v2 = tanh_mufu(D[nt][2]), v3 = tanh_mufu(D[nt][3]);
            u32 p01 = pack_f16x2(v0, v1), p23 = pack_f16x2(v2, v3);
            hh[base + ktl][2 * o] = p01;  hh[base + ktl][2 * o + 1] = p23;
            float2 a01 = f16x2_to_f2(p01), a23 = f16x2_to_f2(p23);
            hl[base + ktl][2 * o]     = pack_f16x2(v0 - a01.x, v1 - a01.y);
            hl[base + ktl][2 * o + 1] = pack_f16x2(v2 - a23.x, v3 - a23.y);
        }
    }
}
// single-barrier combined hi/lo exchange (double-buffered across call sites)
static __device__ __forceinline__ void xchg1(u32 (&hh)[8][4], u32 (&hl)[8][4],
                                             u32 exOwn, u32 exOth, int own, int oth, int barid)
{
    #pragma unroll
    for (int k = 0; k < 4; k++) {
        STS128(exOwn + k * 512, hh[own + k]);
        STS128(exOwn + (k + 4) * 512, hl[own + k]);
    }
    BARS(barid);
    #pragma unroll
    for (int k = 0; k < 4; k++) {
        LDS128(hh[oth + k], exOth + k * 512);
        LDS128(hl[oth + k], exOth + (k + 4) * 512);
    }
}

__global__ void __launch_bounds__(256, 1) rnn_fused(
    const float* __restrict__ x,
    const float* __restrict__ W_ih0, const float* __restrict__ W_hh0,
    const float* __restrict__ b_ih0, const float* __restrict__ b_hh0,
    const float* __restrict__ W_ih1, const float* __restrict__ W_hh1,
    const float* __restrict__ b_ih1, const float* __restrict__ b_hh1,
    const float* __restrict__ fc_w,  const float* __restrict__ fc_b,
    float* __restrict__ out)
{
    extern __shared__ char dyn[];
    const int tid = threadIdx.x;
    const int wid = tid >> 5, lane = tid & 31;
    const int rg = wid & 3, jh = wid >> 2;   // measured-best pairing
    const int g = lane >> 2, p = lane & 3;

    // ---- init: W tiles fp16, swizzled 256B rows ----
    {
        const float* Ws[3] = { W_hh0, W_ih1, W_hh1 };
        #pragma unroll
        for (int m = 0; m < 3; m++) {
            char* dw = dyn + m * 32768;
            const float* W = Ws[m];
            for (int i = tid; i < Hq * Hq; i += 256) {
                int j = i >> 7, k = i & 127;
                u32 a = (u32)(j * 256) + (u32)((2 * k) ^ ((j & 7) << 4));
                *(__half*)(dw + a) = __float2half(W[i]);
            }
        }
        for (int i = tid; i < Hq * 32; i += 256) {   // X tile [j][k pad32], 64B rows
            int j = i >> 5, k = i & 31;
            float v = (k < Iq) ? W_ih0[j * Iq + k] : 0.0f;
            u32 a = (u32)(j * 64) + (u32)((2 * k) ^ ((j & 3) << 4));
            *(__half*)(dyn + OFF_X0 + a) = __float2half(v);
        }
        float* b0s = (float*)(dyn + OFF_B0);
        float* b1s = (float*)(dyn + OFF_B1);
        for (int i = tid; i < Hq; i += 256) {
            b0s[i] = b_ih0[i] + b_hh0[i];
            b1s[i] = b_ih1[i] + b_hh1[i];
        }
    }
    __syncthreads();

    const u32 smb = smem_u32(dyn);
    const u32 r    = (u32)((((lane >> 4) & 1) * 8) + (lane & 7));
    const u32 h16  = (u32)(((lane >> 3) & 1) * 16);
    const u32 swzR = (u32)((lane & 7) << 4);
    const u32 hsR  = r * 256 + (h16 ^ (swzR & 16));
    const u32 sw56 = swzR & 96;
    const u32 swzX = (u32)((lane & 3) << 4);
    const u32 hsX  = r * 64 + (h16 ^ (swzX & 16));
    const u32 sw5x = swzX & 32;

    const u32 W0B = smb + (u32)(jh * 16384);
    const u32 WIB = smb + 32768 + (u32)(jh * 16384);
    const u32 WHB = smb + 65536 + (u32)(jh * 16384);
    const u32 X0B = smb + OFF_X0 + (u32)(jh * 4096);
    const u32 slotOwn = (u32)(((rg * 2 + jh) * 8) * 32 + lane) * 16;
    const u32 slotOth = (u32)(((rg * 2 + 1 - jh) * 8) * 32 + lane) * 16;
    const u32 exAOwn = smb + OFF_EXA + slotOwn, exAOth = smb + OFF_EXA + slotOth;
    const u32 exBOwn = smb + OFF_EXB + slotOwn, exBOth = smb + OFF_EXB + slotOth;
    const int own = jh * 4, oth = (1 - jh) * 4, barid = rg + 1;

    const float* b0s = (float*)(dyn + OFF_B0);
    const float* b1s = (float*)(dyn + OFF_B1);
    const size_t rowA = ((size_t)blockIdx.x * 4 + rg) * 16 + g;
    const float* xA = x + rowA * Tq * Iq;
    const float* xB = x + (rowA + 8) * Tq * Iq;

    u32 h0h[8][4], h0l[8][4], h1h[8][4], h1l[8][4];
    float D[8][4];

    for (int t = 0; t < Tq; t++) {
        // ---- x A-frags (K=32, fp16 hi/lo) ----
        u32 xh[2][4], xl[2][4];
        {
            const float* at = xA + t * Iq;
            const float* bt = xB + t * Iq;
            float2 xv[8];
            xv[0] = *(const float2*)(at + 2 * p);       xv[1] = *(const float2*)(bt + 2 * p);
            xv[2] = *(const float2*)(at + 8 + 2 * p);   xv[3] = *(const float2*)(bt + 8 + 2 * p);
            xv[4] = *(const float2*)(at + 16 + 2 * p);  xv[5] = *(const float2*)(bt + 16 + 2 * p);
            xv[6] = (p < 2) ? *(const float2*)(at + 24 + 2 * p) : make_float2(0.f, 0.f);
            xv[7] = (p < 2) ? *(const float2*)(bt + 24 + 2 * p) : make_float2(0.f, 0.f);
            #pragma unroll
            for (int q = 0; q < 8; q++) {
                u32 hu = pack_f16x2(xv[q].x, xv[q].y);
                float2 av = f16x2_to_f2(hu);
                xh[q >> 2][q & 3] = hu;
                xl[q >> 2][q & 3] = pack_f16x2(xv[q].x - av.x, xv[q].y - av.y);
            }
        }

        // ---- layer 0: D = b0 + h0@W0^T + x@Wih0^T ----
        #pragma unroll
        for (int nt = 0; nt < 8; nt++) {
            float2 bv = *(const float2*)&b0s[jh * 64 + nt * 8 + p * 2];
            D[nt][0] = bv.x; D[nt][1] = bv.y; D[nt][2] = bv.x; D[nt][3] = bv.y;
        }
        if (t > 0) gemm2h(D, h0h, h0l, W0B, hsR, sw56);
        gemm_x2(D, xh, xl, X0B, hsX, sw5x);
        tanh_pack(D, h0h, h0l, own);
        xchg1(h0h, h0l, exAOwn, exAOth, own, oth, barid);   // buffer A

        // ---- layer 1: D = b1 + h1@Whh1^T + h0@Wih1^T ----
        #pragma unroll
        for (int nt = 0; nt < 8; nt++) {
            float2 bv = *(const float2*)&b1s[jh * 64 + nt * 8 + p * 2];
            D[nt][0] = bv.x; D[nt][1] = bv.y; D[nt][2] = bv.x; D[nt][3] = bv.y;
        }
        if (t > 0) gemm2h(D, h1h, h1l, WHB, hsR, sw56);
        gemm2h(D, h0h, h0l, WIB, hsR, sw56);
        if (t < Tq - 1) {
            tanh_pack(D, h1h, h1l, own);
            xchg1(h1h, h1l, exBOwn, exBOth, own, oth, barid);  // buffer B
        } else {
            #pragma unroll
            for (int nt = 0; nt < 8; nt++)
                #pragma unroll
                for (int q = 0; q < 4; q++) D[nt][q] = tanh_mufu(D[nt][q]);
        }
    }

    // ---- FC: out = h1 @ fc_w^T + fc_b ----
    __syncthreads();
    float* fcs  = (float*)(dyn + OFF_EXA);
    float* part = (float*)(dyn + OFF_EXA + 5120);
    for (int i = tid; i < Cq * Hq; i += 256) fcs[i] = fc_w[i];
    __syncthreads();

    float accA[Cq], accB[Cq];
    #pragma unroll
    for (int c = 0; c < Cq; c++) { accA[c] = 0.f; accB[c] = 0.f; }
    #pragma unroll
    for (int nt = 0; nt < 8; nt++) {
        int j = jh * 64 + nt * 8 + p * 2;
        #pragma unroll
        for (int c = 0; c < Cq; c++) {
            float2 fw = *(const float2*)&fcs[c * Hq + j];
            accA[c] = fmaf(D[nt][0], fw.x, fmaf(D[nt][1], fw.y, accA[c]));
            accB[c] = fmaf(D[nt][2], fw.x, fmaf(D[nt][3], fw.y, accB[c]));
        }
    }
    #pragma unroll
    for (int c = 0; c < Cq; c++) {
        accA[c] += __shfl_xor_sync(0xFFFFFFFFu, accA[c], 1);
        accA[c] += __shfl_xor_sync(0xFFFFFFFFu, accA[c], 2);
        accB[c] += __shfl_xor_sync(0xFFFFFFFFu, accB[c], 1);
        accB[c] += __shfl_xor_sync(0xFFFFFFFFu, accB[c], 2);
    }
    if (p == 0) {
        int base = (rg * 2 + jh) * 16;
        #pragma unroll
        for (int c = 0; c < Cq; c++) {
            part[(base + g) * Cq + c]     = accA[c];
            part[(base + g + 8) * Cq + c] = accB[c];
        }
    }
    __syncthreads();
    for (int i = tid; i < 64 * Cq; i += 256) {
        int row = i / Cq, c = i - row * Cq;
        int rg2 = row >> 4, rr = row & 15;
        float v = fc_b[c] + part[((rg2 * 2) * 16 + rr) * Cq + c]
                          + part[((rg2 * 2 + 1) * 16 + rr) * Cq + c];
        out[((size_t)blockIdx.x * 64 + row) * Cq + c] = v;
    }
}

extern "C" void kernel_launch(void* const* d_in, const int* in_sizes, int n_in,
                              void* d_out, int out_size) {
    const float* x     = (const float*)d_in[0];
    const float* W_ih0 = (const float*)d_in[1];
    const float* W_hh0 = (const float*)d_in[2];
    const float* b_ih0 = (const float*)d_in[3];
    const float* b_hh0 = (const float*)d_in[4];
    const float* W_ih1 = (const float*)d_in[5];
    const float* W_hh1 = (const float*)d_in[6];
    const float* b_ih1 = (const float*)d_in[7];
    const float* b_hh1 = (const float*)d_in[8];
    const float* fc_w  = (const float*)d_in[9];
    const float* fc_b  = (const float*)d_in[10];
    float* out = (float*)d_out;

    cudaFuncSetAttribute(rnn_fused, cudaFuncAttributeMaxDynamicSharedMemorySize, SMEM_DYN);
    rnn_fused<<<128, 256, SMEM_DYN>>>(x, W_ih0, W_hh0, b_ih0, b_hh0,
                                      W_ih1, W_hh1, b_ih1, b_hh1, fc_w, fc_b, out);
}